// round 9
// baseline (speedup 1.0000x reference)
#include <cuda_runtime.h>
#include <math.h>
#include <float.h>
#include <stdint.h>

#define NN   4096
#define HID  256
#define VD   64
#define RANK0 1228

__device__ __align__(128) float  g_value[2ull * NN * HID];  // (b, j, h*64+k)
__device__ float2 g_stats[2 * NN];                          // (rank1228, rank1229)

__device__ __forceinline__ unsigned flipf(float f) {
    unsigned u = __float_as_uint(f);
    return u ^ (((unsigned)((int)u >> 31)) | 0x80000000u);
}
__device__ __forceinline__ float unflipf(unsigned k) {
    unsigned mask = (k & 0x80000000u) ? 0x80000000u : 0xFFFFFFFFu;
    return __uint_as_float(k ^ mask);
}
__device__ __forceinline__ void cpa16(uint32_t dst, const void* src) {
    asm volatile("cp.async.cg.shared.global [%0], [%1], 16;" :: "r"(dst), "l"(src));
}

#define PACK_F32X2(out, lo, hi) \
    asm("mov.b64 %0, {%1, %2};" : "=l"(out) : "f"(lo), "f"(hi))
#define UNPACK_F32X2(lo, hi, in) \
    asm("mov.b64 {%0, %1}, %2;" : "=f"(lo), "=f"(hi) : "l"(in))
#define FMA_F32X2(d, a, b, c) \
    asm("fma.rn.f32x2 %0, %1, %2, %3;" : "=l"(d) : "l"(a), "l"(b), "l"(c))

// ---------------------------------------------------------------------------
// fused pre-kernel: blocks [0,256) -> g_value ; blocks [256,8448) -> g_stats
// ---------------------------------------------------------------------------
__global__ void __launch_bounds__(256) k_pre(const float* __restrict__ x,
                                             const float* __restrict__ wgt,
                                             const float* __restrict__ m) {
    __shared__ __align__(16) float u_sm[9248];
    const int t = threadIdx.x;

    if (blockIdx.x < 256) {
        // ---- value branch (R6 verbatim) ----
        float* wsh = u_sm;              // 32 x 256
        float* xsh = u_sm + 8192;       // 32 x 33
        const size_t base = (size_t)blockIdx.x * 32 * HID;
        const int jj = t >> 3, cg = t & 7;
        float4 acc[8];
#pragma unroll
        for (int q = 0; q < 8; ++q) acc[q] = make_float4(0.f, 0.f, 0.f, 0.f);
        for (int ct = 0; ct < 8; ++ct) {
            __syncthreads();
#pragma unroll
            for (int s = 0; s < 32; ++s) {
                int idx = t + 256 * s;
                int cc = idx >> 8, col = idx & 255;
                wsh[idx] = wgt[(col >> 6) * 16384 + (ct * 32 + cc) * 64 + (col & 63)];
            }
#pragma unroll
            for (int s = 0; s < 4; ++s) {
                int idx = t + 256 * s;
                int jr = idx >> 5, cc = idx & 31;
                xsh[jr * 33 + cc] = x[base + (size_t)jr * HID + ct * 32 + cc];
            }
            __syncthreads();
#pragma unroll 4
            for (int cc = 0; cc < 32; ++cc) {
                float xv = xsh[jj * 33 + cc];
#pragma unroll
                for (int qq = 0; qq < 8; ++qq) {
                    int qe = (qq + cg) & 7;
                    float4 wv = *(const float4*)(wsh + cc * 256 + cg * 32 + qe * 4);
                    acc[qq].x = fmaf(xv, wv.x, acc[qq].x);
                    acc[qq].y = fmaf(xv, wv.y, acc[qq].y);
                    acc[qq].z = fmaf(xv, wv.z, acc[qq].z);
                    acc[qq].w = fmaf(xv, wv.w, acc[qq].w);
                }
            }
        }
        float* orow = g_value + base + (size_t)jj * HID + cg * 32;
#pragma unroll
        for (int qq = 0; qq < 8; ++qq) {
            int qe = (qq + cg) & 7;
            *(float4*)(orow + qe * 4) = acc[qq];
        }
        return;
    }

    // ---- stats branch: warp-aggregated compaction + parallel bin scan ----
    const int row = blockIdx.x - 256;
    const float* p = m + (size_t)row * NN;
    unsigned* list = (unsigned*)u_sm;            // 4096 entries
    unsigned* hist = (unsigned*)(u_sm + 4096);   // 256 entries
    __shared__ unsigned s_prefix, s_mingt;
    __shared__ int s_cnt, s_clo, s_want, s_cle;
    const int lane = t & 31;

    int c_lo = 0, n = 0;
    for (int attempt = 0; attempt < 2; ++attempt) {
        float lo = attempt ? -FLT_MAX : 0.26f;
        float hi = attempt ?  FLT_MAX : 0.34f;
        __syncthreads();
        if (t == 0) { s_cnt = 0; s_clo = 0; }
        __syncthreads();
        int my_lo = 0;
#pragma unroll
        for (int s = 0; s < 4; ++s) {
            float4 v = *(const float4*)(p + 4 * (t + 256 * s));
            float f[4] = {v.x, v.y, v.z, v.w};
#pragma unroll
            for (int l = 0; l < 4; ++l) {
                bool is_lo = (f[l] < lo);
                bool keep  = !is_lo && (attempt || f[l] < hi);
                if (is_lo) my_lo++;
                unsigned bal = __ballot_sync(0xffffffffu, keep);
                if (keep) {
                    int lead = __ffs(bal) - 1;
                    int pos;
                    if (lane == lead) pos = atomicAdd(&s_cnt, __popc(bal));
                    pos = __shfl_sync(bal, pos, lead);
                    pos += __popc(bal & ((1u << lane) - 1u));
                    list[pos] = flipf(f[l]);
                }
            }
        }
        if (my_lo) atomicAdd(&s_clo, my_lo);
        __syncthreads();
        c_lo = s_clo; n = s_cnt;
        if (c_lo <= RANK0 && c_lo + n >= RANK0 + 2) break;
    }

    unsigned prefix = 0;
    int want = RANK0 - c_lo;
    for (int shift = 24; shift >= 0; shift -= 8) {
        __syncthreads();
        hist[t] = 0;
        __syncthreads();
        unsigned sel_mask = (shift == 24) ? 0u : (0xFFFFFFFFu << (shift + 8));
        for (int i = t; i < n; i += 256) {
            unsigned k = list[i];
            if ((k & sel_mask) == prefix) atomicAdd(&hist[(k >> shift) & 255], 1u);
        }
        __syncthreads();
        unsigned hv = hist[t];
        // Hillis-Steele inclusive scan over 256 bins
        for (int d = 1; d < 256; d <<= 1) {
            unsigned addv = (t >= d) ? hist[t - d] : 0u;
            __syncthreads();
            hist[t] += addv;
            __syncthreads();
        }
        int incl = (int)hist[t];
        int excl = incl - (int)hv;
        if (excl <= want && want < incl) {      // exactly one t (hv>0) matches
            s_prefix = prefix | ((unsigned)t << shift);
            s_want = want - excl;
        }
        __syncthreads();
        prefix = s_prefix; want = s_want;
    }
    unsigned key_a = prefix;

    __syncthreads();
    if (t == 0) { s_cle = 0; s_mingt = 0xFFFFFFFFu; }
    __syncthreads();
    int cle = 0; unsigned mgt = 0xFFFFFFFFu;
    for (int i = t; i < n; i += 256) {
        unsigned k = list[i];
        if (k <= key_a) cle++;
        else if (k < mgt) mgt = k;
    }
    atomicAdd((unsigned*)&s_cle, (unsigned)cle);
    atomicMin(&s_mingt, mgt);
    __syncthreads();
    if (t == 0) {
        unsigned key_b = (c_lo + s_cle >= RANK0 + 2) ? key_a : s_mingt;
        g_stats[row] = make_float2(unflipf(key_a), unflipf(key_b));
    }
}

// ---------------------------------------------------------------------------
// main: R6 structure; inner product via packed fma.rn.f32x2 (FFMA2)
// dyn smem: m[2][4096] | v[2][4096]. grid (64,4,2), 256 thr, 2 CTAs/SM.
// ---------------------------------------------------------------------------
__global__ void __launch_bounds__(256, 2) k_main(const float* __restrict__ m,
                                                 const float* __restrict__ r,
                                                 float* __restrict__ out) {
    extern __shared__ __align__(16) float sm[];   // [0,8192): m bufs, [8192,16384): v bufs
    __shared__ float wsm[64 * 68];    // w[j][i], stride 68
    __shared__ float thr_s[64];
    __shared__ float dbuf[256];

    const int t  = threadIdx.x;
    const int kg = t & 7, ig = (t >> 3) & 7, js = t >> 6;
    const int h  = blockIdx.y, bz = blockIdx.z;
    const int i_base = blockIdx.x * 64;

    const float rv = r[h];
    const float r2 = __fmul_rn(rv, rv);
    if (t < 64) {
        float2 st = g_stats[bz * NN + i_base + t];
        thr_s[t] = __fadd_rn(__fmul_rn(0.5f, __fmul_rn(r2, st.x)),
                             __fmul_rn(0.5f, __fmul_rn(r2, st.y)));
    }

    const float* mrow = m + ((size_t)bz * NN + i_base) * NN;
    const float* vsrc = g_value + (size_t)bz * NN * HID + h * VD;
    uint32_t sm_u = (uint32_t)__cvta_generic_to_shared(sm);

    uint64_t acc2[32];                 // acc2[a*4+q] = (k=2q, k=2q+1) for row a
#pragma unroll
    for (int q = 0; q < 32; ++q) acc2[q] = 0ull;
    float den8[8];
#pragma unroll
    for (int a = 0; a < 8; ++a) den8[a] = 0.f;

    // preload tile 0
#pragma unroll
    for (int s = 0; s < 4; ++s) {
        int q = t + 256 * s;
        cpa16(sm_u + (unsigned)q * 16, mrow + (size_t)(q >> 4) * NN + (q & 15) * 4);
    }
#pragma unroll
    for (int s = 0; s < 4; ++s) {
        int q = t + 256 * s;
        cpa16(sm_u + 32768u + (unsigned)q * 16, vsrc + (size_t)(q >> 4) * HID + (q & 15) * 4);
    }
    asm volatile("cp.async.commit_group;");

    for (int jt = 0; jt < 64; ++jt) {
        const int buf = jt & 1;
        if (jt < 63) {
            const int j0n = (jt + 1) * 64;
            const unsigned bo = (unsigned)((jt + 1) & 1);
#pragma unroll
            for (int s = 0; s < 4; ++s) {
                int q = t + 256 * s;
                cpa16(sm_u + bo * 16384u + (unsigned)q * 16,
                      mrow + (size_t)(q >> 4) * NN + j0n + (q & 15) * 4);
            }
#pragma unroll
            for (int s = 0; s < 4; ++s) {
                int q = t + 256 * s;
                cpa16(sm_u + 32768u + bo * 16384u + (unsigned)q * 16,
                      vsrc + (size_t)(j0n + (q >> 4)) * HID + (q & 15) * 4);
            }
            asm volatile("cp.async.commit_group;");
            asm volatile("cp.async.wait_group 1;");
        } else {
            asm volatile("cp.async.wait_group 0;");
        }
        __syncthreads();

        // w-stage (R6 verbatim)
        {
            const float* mb = sm + buf * 4096;
#pragma unroll
            for (int s = 0; s < 16; ++s) {
                int e = t + 256 * s;
                int ii = e >> 6, jj = e & 63;
                float sv = __fmul_rn(mb[ii * 64 + jj], r2);
                wsm[jj * 68 + ii] = (sv <= thr_s[ii]) ? __expf(-sv) : 0.f;
            }
        }
        __syncthreads();

        // compute: packed f32x2 FMAs, same accumulation order as R6
        {
            const float* wrow = wsm + ig * 8;
            const float* vrow = sm + 8192 + buf * 4096 + kg * 8;
#pragma unroll 4
            for (int jj = 0; jj < 16; ++jj) {
                int j = js * 16 + jj;
                float4 w0 = *(const float4*)(wrow + j * 68);
                float4 w1 = *(const float4*)(wrow + j * 68 + 4);
                const float* vj = vrow + j * 64;
                uint64_t v2[4];
                v2[0] = *(const uint64_t*)(vj + 0);
                v2[1] = *(const uint64_t*)(vj + 2);
                v2[2] = *(const uint64_t*)(vj + 4);
                v2[3] = *(const uint64_t*)(vj + 6);
                float wv[8] = {w0.x, w0.y, w0.z, w0.w, w1.x, w1.y, w1.z, w1.w};
#pragma unroll
                for (int a = 0; a < 8; ++a) {
                    uint64_t wd;
                    PACK_F32X2(wd, wv[a], wv[a]);
#pragma unroll
                    for (int q = 0; q < 4; ++q)
                        FMA_F32X2(acc2[a * 4 + q], wd, v2[q], acc2[a * 4 + q]);
                }
                if (kg == 0) {
#pragma unroll
                    for (int a = 0; a < 8; ++a) den8[a] += wv[a];
                }
            }
        }
        __syncthreads();
    }

    // unpack accumulators
    float accf[64];
#pragma unroll
    for (int a = 0; a < 8; ++a)
#pragma unroll
        for (int q = 0; q < 4; ++q)
            UNPACK_F32X2(accf[a * 8 + 2 * q], accf[a * 8 + 2 * q + 1], acc2[a * 4 + q]);

    // ---- epilogue (R6 verbatim, on accf) ----
    if (kg == 0) {
#pragma unroll
        for (int a = 0; a < 8; ++a) dbuf[js * 64 + ig * 8 + a] = den8[a];
    }

    float* red = sm;
    const int t64 = t & 63;
#pragma unroll
    for (int rr = 0; rr < 4; ++rr) {
        __syncthreads();
        if (js > 0) {
#pragma unroll
            for (int q = 0; q < 16; ++q)
                red[(js - 1) * 1024 + t64 * 16 + q] = accf[rr * 16 + q];
        }
        __syncthreads();
        if (js == 0) {
#pragma unroll
            for (int pp = 0; pp < 3; ++pp)
#pragma unroll
                for (int q = 0; q < 16; ++q)
                    accf[rr * 16 + q] += red[pp * 1024 + t64 * 16 + q];
        }
    }

    if (js == 0) {
#pragma unroll
        for (int a = 0; a < 8; ++a) {
            int il = ig * 8 + a;
            float den = dbuf[il] + dbuf[64 + il] + dbuf[128 + il] + dbuf[192 + il];
            float inv = 1.0f / den;
            float o[8];
#pragma unroll
            for (int b2 = 0; b2 < 8; ++b2) {
                float v = accf[a * 8 + b2] * inv;
                o[b2] = 0.5f * v * (1.0f + erff(v * 0.7071067811865475f));
            }
            float* op = out + ((size_t)bz * NN + i_base + il) * HID + h * VD + kg * 8;
            *(float4*)op       = make_float4(o[0], o[1], o[2], o[3]);
            *(float4*)(op + 4) = make_float4(o[4], o[5], o[6], o[7]);
        }
    }
}

// ---------------------------------------------------------------------------
extern "C" void kernel_launch(void* const* d_in, const int* in_sizes, int n_in,
                              void* d_out, int out_size) {
    const float *m = nullptr, *x = nullptr, *r = nullptr, *w = nullptr;
    for (int i = 0; i < n_in; ++i) {
        int s = in_sizes[i];
        if      (s == 33554432) m = (const float*)d_in[i];
        else if (s == 2097152)  x = (const float*)d_in[i];
        else if (s == 4)        r = (const float*)d_in[i];
        else if (s == 65536)    w = (const float*)d_in[i];
    }
    float* out = (float*)d_out;

    const int smem_main = 16384 * 4;   // 64 KB dynamic
    cudaFuncSetAttribute(k_main, cudaFuncAttributeMaxDynamicSharedMemorySize, smem_main);

    k_pre<<<256 + 8192, 256>>>(x, w, m);
    k_main<<<dim3(64, 4, 2), 256, smem_main>>>(m, r, out);
}

// round 11
// speedup vs baseline: 1.7739x; 1.7739x over previous
#include <cuda_runtime.h>
#include <cuda_fp16.h>
#include <math.h>
#include <float.h>
#include <stdint.h>

#define NN 4096
#define HID 256
#define RANK0 1228

// k_mma dyn smem byte offsets
#define MOF 0u
#define MBS 18432u     // m buf: 128 x 36 floats
#define WHO 36864u
#define WBS 10240u     // w buf: 128 x 40 halves
#define WLO 57344u
#define VHO 77824u
#define VBS 5120u      // v buf: 64 x 40 halves
#define VLO 88064u
#define SMT 98304

__device__ __align__(128) float  g_value[2ull * NN * HID];   // (b, j, h*64+k)
__device__ float2 g_stats[2 * NN];
__device__ __align__(128) __half g_vhi[8ull * 64 * NN];      // (b*4+h, k, j)
__device__ __align__(128) __half g_vlo[8ull * 64 * NN];

__device__ __forceinline__ unsigned flipf(float f) {
    unsigned u = __float_as_uint(f);
    return u ^ (((unsigned)((int)u >> 31)) | 0x80000000u);
}
__device__ __forceinline__ float unflipf(unsigned k) {
    unsigned mask = (k & 0x80000000u) ? 0x80000000u : 0xFFFFFFFFu;
    return __uint_as_float(k ^ mask);
}
__device__ __forceinline__ void cpa16(uint32_t dst, const void* src) {
    asm volatile("cp.async.cg.shared.global [%0], [%1], 16;" :: "r"(dst), "l"(src));
}
__device__ __forceinline__ uint32_t pk(__half a, __half b) {
    __half2 h = __halves2half2(a, b);
    return *(uint32_t*)&h;
}
#define LDSM4(r0, r1, r2, r3, a) \
    asm volatile("ldmatrix.sync.aligned.m8n8.x4.shared.b16 {%0,%1,%2,%3},[%4];" \
        : "=r"(r0), "=r"(r1), "=r"(r2), "=r"(r3) : "r"(a))
#define MMA(d, a0, a1, a2, a3, b0, b1) \
    asm volatile("mma.sync.aligned.m16n8k16.row.col.f32.f16.f16.f32 " \
        "{%0,%1,%2,%3},{%4,%5,%6,%7},{%8,%9},{%0,%1,%2,%3};" \
        : "+f"((d)[0]), "+f"((d)[1]), "+f"((d)[2]), "+f"((d)[3]) \
        : "r"(a0), "r"(a1), "r"(a2), "r"(a3), "r"(b0), "r"(b1))

// ---------------------------------------------------------------------------
// k_pre: blocks [0,256) -> g_value ; [256,8448) -> g_stats  (proven verbatim)
// ---------------------------------------------------------------------------
__global__ void __launch_bounds__(256) k_pre(const float* __restrict__ x,
                                             const float* __restrict__ wgt,
                                             const float* __restrict__ m) {
    __shared__ __align__(16) float u_sm[9248];
    const int t = threadIdx.x;
    if (blockIdx.x < 256) {
        float* wsh = u_sm;
        float* xsh = u_sm + 8192;
        const size_t base = (size_t)blockIdx.x * 32 * HID;
        const int jj = t >> 3, cg = t & 7;
        float4 acc[8];
#pragma unroll
        for (int q = 0; q < 8; ++q) acc[q] = make_float4(0.f, 0.f, 0.f, 0.f);
        for (int ct = 0; ct < 8; ++ct) {
            __syncthreads();
#pragma unroll
            for (int s = 0; s < 32; ++s) {
                int idx = t + 256 * s;
                int cc = idx >> 8, col = idx & 255;
                wsh[idx] = wgt[(col >> 6) * 16384 + (ct * 32 + cc) * 64 + (col & 63)];
            }
#pragma unroll
            for (int s = 0; s < 4; ++s) {
                int idx = t + 256 * s;
                int jr = idx >> 5, cc = idx & 31;
                xsh[jr * 33 + cc] = x[base + (size_t)jr * HID + ct * 32 + cc];
            }
            __syncthreads();
#pragma unroll 4
            for (int cc = 0; cc < 32; ++cc) {
                float xv = xsh[jj * 33 + cc];
#pragma unroll
                for (int qq = 0; qq < 8; ++qq) {
                    int qe = (qq + cg) & 7;
                    float4 wv = *(const float4*)(wsh + cc * 256 + cg * 32 + qe * 4);
                    acc[qq].x = fmaf(xv, wv.x, acc[qq].x);
                    acc[qq].y = fmaf(xv, wv.y, acc[qq].y);
                    acc[qq].z = fmaf(xv, wv.z, acc[qq].z);
                    acc[qq].w = fmaf(xv, wv.w, acc[qq].w);
                }
            }
        }
        float* orow = g_value + base + (size_t)jj * HID + cg * 32;
#pragma unroll
        for (int qq = 0; qq < 8; ++qq) {
            int qe = (qq + cg) & 7;
            *(float4*)(orow + qe * 4) = acc[qq];
        }
        return;
    }
    const int row = blockIdx.x - 256;
    const float* p = m + (size_t)row * NN;
    unsigned* list = (unsigned*)u_sm;
    unsigned* hist = (unsigned*)(u_sm + 4096);
    __shared__ unsigned s_prefix, s_mingt;
    __shared__ int s_cnt, s_clo, s_want, s_cle;
    const int lane = t & 31;
    int c_lo = 0, n = 0;
    for (int attempt = 0; attempt < 2; ++attempt) {
        float lo = attempt ? -FLT_MAX : 0.26f;
        float hi = attempt ?  FLT_MAX : 0.34f;
        __syncthreads();
        if (t == 0) { s_cnt = 0; s_clo = 0; }
        __syncthreads();
        int my_lo = 0;
#pragma unroll
        for (int s = 0; s < 4; ++s) {
            float4 v = *(const float4*)(p + 4 * (t + 256 * s));
            float f[4] = {v.x, v.y, v.z, v.w};
#pragma unroll
            for (int l = 0; l < 4; ++l) {
                bool is_lo = (f[l] < lo);
                bool keep  = !is_lo && (attempt || f[l] < hi);
                if (is_lo) my_lo++;
                unsigned bal = __ballot_sync(0xffffffffu, keep);
                if (keep) {
                    int lead = __ffs(bal) - 1;
                    int pos;
                    if (lane == lead) pos = atomicAdd(&s_cnt, __popc(bal));
                    pos = __shfl_sync(bal, pos, lead);
                    pos += __popc(bal & ((1u << lane) - 1u));
                    list[pos] = flipf(f[l]);
                }
            }
        }
        if (my_lo) atomicAdd(&s_clo, my_lo);
        __syncthreads();
        c_lo = s_clo; n = s_cnt;
        if (c_lo <= RANK0 && c_lo + n >= RANK0 + 2) break;
    }
    unsigned prefix = 0;
    int want = RANK0 - c_lo;
    for (int shift = 24; shift >= 0; shift -= 8) {
        __syncthreads();
        hist[t] = 0;
        __syncthreads();
        unsigned sel_mask = (shift == 24) ? 0u : (0xFFFFFFFFu << (shift + 8));
        for (int i = t; i < n; i += 256) {
            unsigned k = list[i];
            if ((k & sel_mask) == prefix) atomicAdd(&hist[(k >> shift) & 255], 1u);
        }
        __syncthreads();
        unsigned hv = hist[t];
        for (int d = 1; d < 256; d <<= 1) {
            unsigned addv = (t >= d) ? hist[t - d] : 0u;
            __syncthreads();
            hist[t] += addv;
            __syncthreads();
        }
        int incl = (int)hist[t];
        int excl = incl - (int)hv;
        if (excl <= want && want < incl) {
            s_prefix = prefix | ((unsigned)t << shift);
            s_want = want - excl;
        }
        __syncthreads();
        prefix = s_prefix; want = s_want;
    }
    unsigned key_a = prefix;
    __syncthreads();
    if (t == 0) { s_cle = 0; s_mingt = 0xFFFFFFFFu; }
    __syncthreads();
    int cle = 0; unsigned mgt = 0xFFFFFFFFu;
    for (int i = t; i < n; i += 256) {
        unsigned k = list[i];
        if (k <= key_a) cle++;
        else if (k < mgt) mgt = k;
    }
    atomicAdd((unsigned*)&s_cle, (unsigned)cle);
    atomicMin(&s_mingt, mgt);
    __syncthreads();
    if (t == 0) {
        unsigned key_b = (c_lo + s_cle >= RANK0 + 2) ? key_a : s_mingt;
        g_stats[row] = make_float2(unflipf(key_a), unflipf(key_b));
    }
}

// ---------------------------------------------------------------------------
// k_vt: g_value (b,j,h*64+k) -> g_vhi/g_vlo (b*4+h, k, j) fp16 hi/lo split
// ---------------------------------------------------------------------------
__global__ void __launch_bounds__(256) k_vt() {
    __shared__ float ts[64][65];
    const int t = threadIdx.x;
    const int bh = blockIdx.x >> 6, jt = blockIdx.x & 63;
#pragma unroll
    for (int s = 0; s < 4; ++s) {
        int idx = t + 256 * s;
        int jj = idx >> 4, q = idx & 15;
        float4 v = *(const float4*)(g_value +
            ((size_t)(bh >> 2) * NN + jt * 64 + jj) * HID + (bh & 3) * 64 + q * 4);
        ts[jj][q * 4 + 0] = v.x; ts[jj][q * 4 + 1] = v.y;
        ts[jj][q * 4 + 2] = v.z; ts[jj][q * 4 + 3] = v.w;
    }
    __syncthreads();
    const int k = t >> 2, seg = t & 3;
    uint32_t uh[8], ul[8];
#pragma unroll
    for (int e = 0; e < 8; ++e) {
        float v0 = ts[seg * 16 + 2 * e][k], v1 = ts[seg * 16 + 2 * e + 1][k];
        __half h0 = __float2half_rn(v0), h1 = __float2half_rn(v1);
        uh[e] = pk(h0, h1);
        ul[e] = pk(__float2half_rn(v0 - __half2float(h0)),
                   __float2half_rn(v1 - __half2float(h1)));
    }
    size_t dst = ((size_t)(bh * 64 + k)) * NN + jt * 64 + seg * 16;
    *(uint4*)(g_vhi + dst)     = make_uint4(uh[0], uh[1], uh[2], uh[3]);
    *(uint4*)(g_vhi + dst + 8) = make_uint4(uh[4], uh[5], uh[6], uh[7]);
    *(uint4*)(g_vlo + dst)     = make_uint4(ul[0], ul[1], ul[2], ul[3]);
    *(uint4*)(g_vlo + dst + 8) = make_uint4(ul[4], ul[5], ul[6], ul[7]);
}

// ---------------------------------------------------------------------------
// k_mma: CTA = (128 i, h, b). j-tiles of 32; mma.sync m16n8k16 f16 hi/lo x3.
// warp w owns i rows [w*16, w*16+16), 8 n-tiles of 8 k-cols, 32 f32 acc regs.
// ---------------------------------------------------------------------------
__global__ void __launch_bounds__(256, 2) k_mma(const float* __restrict__ m,
                                                const float* __restrict__ r,
                                                float* __restrict__ out) {
    extern __shared__ __align__(16) char sgen[];
    __shared__ float thr_s[128];
    const int t = threadIdx.x, warp = t >> 5, lane = t & 31;
    const int h = blockIdx.y, bz = blockIdx.z;
    const int i_base = blockIdx.x * 128;
    const int bh64 = (bz * 4 + h) * 64;
    const uint32_t sb = (uint32_t)__cvta_generic_to_shared(sgen);

    const float rv = r[h], r2 = __fmul_rn(rv, rv);
    if (t < 128) {
        float2 st = g_stats[bz * NN + i_base + t];
        thr_s[t] = __fadd_rn(__fmul_rn(0.5f, __fmul_rn(r2, st.x)),
                             __fmul_rn(0.5f, __fmul_rn(r2, st.y)));
    }
    __syncthreads();

    const int i = t & 127, jh = t >> 7;
    const float* mbase = m + (size_t)(bz * NN + i_base) * NN;
    const float thr_i = thr_s[i];
    float den_acc = 0.f;
    float acc[32];
#pragma unroll
    for (int q = 0; q < 32; ++q) acc[q] = 0.f;

    // prologue: tile 0 copies
    {
#pragma unroll
        for (int s = 0; s < 4; ++s) {
            int idx = t + 256 * s;
            int i2 = idx >> 3, q = idx & 7;
            cpa16(sb + MOF + (unsigned)i2 * 144u + (unsigned)q * 16u,
                  mbase + (size_t)i2 * NN + q * 4);
        }
        int k2 = t >> 2, q = t & 3;
        cpa16(sb + VHO + (unsigned)k2 * 80u + (unsigned)q * 16u,
              g_vhi + (size_t)(bh64 + k2) * NN + q * 8);
        cpa16(sb + VLO + (unsigned)k2 * 80u + (unsigned)q * 16u,
              g_vlo + (size_t)(bh64 + k2) * NN + q * 8);
        asm volatile("cp.async.commit_group;");
    }

    for (int c = 0; c < 128; ++c) {
        const unsigned buf = (unsigned)(c & 1);
        if (c < 127) {
            const int j0n = (c + 1) * 32;
            const unsigned nb = (unsigned)((c + 1) & 1);
#pragma unroll
            for (int s = 0; s < 4; ++s) {
                int idx = t + 256 * s;
                int i2 = idx >> 3, q = idx & 7;
                cpa16(sb + MOF + nb * MBS + (unsigned)i2 * 144u + (unsigned)q * 16u,
                      mbase + (size_t)i2 * NN + j0n + q * 4);
            }
            int k2 = t >> 2, q = t & 3;
            cpa16(sb + VHO + nb * VBS + (unsigned)k2 * 80u + (unsigned)q * 16u,
                  g_vhi + (size_t)(bh64 + k2) * NN + j0n + q * 8);
            cpa16(sb + VLO + nb * VBS + (unsigned)k2 * 80u + (unsigned)q * 16u,
                  g_vlo + (size_t)(bh64 + k2) * NN + j0n + q * 8);
            asm volatile("cp.async.commit_group;");
            asm volatile("cp.async.wait_group 1;");
        } else {
            asm volatile("cp.async.wait_group 0;");
        }
        __syncthreads();

        // w-stage: 16 j per thread; exp/mask, fp16 split, den accumulate
        {
            const float* ms = (const float*)(sgen + MOF + buf * MBS) + i * 36 + jh * 16;
            float w[16];
#pragma unroll
            for (int q = 0; q < 4; ++q) {
                float4 mv = *(const float4*)(ms + q * 4);
                float s0 = __fmul_rn(mv.x, r2), s1 = __fmul_rn(mv.y, r2);
                float s2 = __fmul_rn(mv.z, r2), s3 = __fmul_rn(mv.w, r2);
                w[q * 4 + 0] = (s0 <= thr_i) ? __expf(-s0) : 0.f;
                w[q * 4 + 1] = (s1 <= thr_i) ? __expf(-s1) : 0.f;
                w[q * 4 + 2] = (s2 <= thr_i) ? __expf(-s2) : 0.f;
                w[q * 4 + 3] = (s3 <= thr_i) ? __expf(-s3) : 0.f;
            }
#pragma unroll
            for (int q = 0; q < 16; ++q) den_acc += w[q];
            uint32_t uh[8], ul[8];
#pragma unroll
            for (int e = 0; e < 8; ++e) {
                __half h0 = __float2half_rn(w[2 * e]), h1 = __float2half_rn(w[2 * e + 1]);
                uh[e] = pk(h0, h1);
                ul[e] = pk(__float2half_rn(w[2 * e] - __half2float(h0)),
                           __float2half_rn(w[2 * e + 1] - __half2float(h1)));
            }
            char* wd = sgen + WHO + buf * WBS + i * 80 + jh * 32;
            *(uint4*)wd        = make_uint4(uh[0], uh[1], uh[2], uh[3]);
            *(uint4*)(wd + 16) = make_uint4(uh[4], uh[5], uh[6], uh[7]);
            char* ld = wd + (WLO - WHO);
            *(uint4*)ld        = make_uint4(ul[0], ul[1], ul[2], ul[3]);
            *(uint4*)(ld + 16) = make_uint4(ul[4], ul[5], ul[6], ul[7]);
        }
        __syncthreads();

        // mma stage
        {
            const int i0 = warp * 16;
            const unsigned arow = (unsigned)(i0 + (lane & 15)) * 80u +
                                  (unsigned)((lane >> 4) << 4);
            const int nb_ = (lane & 7) + ((lane >> 4) << 3);
            const unsigned brow0 = (unsigned)nb_ * 80u + (unsigned)((lane & 8) << 1);
#pragma unroll
            for (int cc = 0; cc < 2; ++cc) {
                uint32_t ah0, ah1, ah2, ah3, al0, al1, al2, al3;
                uint32_t aaddr = sb + WHO + buf * WBS + arow + (unsigned)cc * 32u;
                LDSM4(ah0, ah1, ah2, ah3, aaddr);
                LDSM4(al0, al1, al2, al3, aaddr + (WLO - WHO));
#pragma unroll
                for (int g = 0; g < 4; ++g) {
                    uint32_t bh0, bh1, bh2, bh3, bl0, bl1, bl2, bl3;
                    uint32_t baddr = sb + VHO + buf * VBS + brow0 +
                                     (unsigned)(g * 16) * 80u + (unsigned)cc * 32u;
                    LDSM4(bh0, bh1, bh2, bh3, baddr);
                    LDSM4(bl0, bl1, bl2, bl3, baddr + (VLO - VHO));
                    float* d0 = acc + g * 8;
                    float* d1 = acc + g * 8 + 4;
                    MMA(d0, ah0, ah1, ah2, ah3, bh0, bh1);
                    MMA(d0, ah0, ah1, ah2, ah3, bl0, bl1);
                    MMA(d0, al0, al1, al2, al3, bh0, bh1);
                    MMA(d1, ah0, ah1, ah2, ah3, bh2, bh3);
                    MMA(d1, ah0, ah1, ah2, ah3, bl2, bl3);
                    MMA(d1, al0, al1, al2, al3, bh2, bh3);
                }
            }
        }
        __syncthreads();
    }

    // epilogue: denominators, gelu, store
    float* sden = (float*)sgen;
    sden[t] = den_acc;
    __syncthreads();
    if (t < 128) sden[256 + t] = sden[t] + sden[t + 128];
    __syncthreads();
    const float* dden = sden + 256;
    const int i0 = warp * 16;
    const int r0 = lane >> 2, c0 = (lane & 3) * 2;
    const float inv0 = 1.0f / dden[i0 + r0];
    const float inv1 = 1.0f / dden[i0 + r0 + 8];
    float* ob = out + ((size_t)(bz * NN + i_base + i0)) * HID + h * 64;
#pragma unroll
    for (int nt = 0; nt < 8; ++nt) {
        float v0 = acc[nt * 4 + 0] * inv0, v1 = acc[nt * 4 + 1] * inv0;
        float v2 = acc[nt * 4 + 2] * inv1, v3 = acc[nt * 4 + 3] * inv1;
        float g0 = 0.5f * v0 * (1.0f + erff(v0 * 0.7071067811865475f));
        float g1 = 0.5f * v1 * (1.0f + erff(v1 * 0.7071067811865475f));
        float g2 = 0.5f * v2 * (1.0f + erff(v2 * 0.7071067811865475f));
        float g3 = 0.5f * v3 * (1.0f + erff(v3 * 0.7071067811865475f));
        *(float2*)(ob + (size_t)r0 * HID + nt * 8 + c0)       = make_float2(g0, g1);
        *(float2*)(ob + (size_t)(r0 + 8) * HID + nt * 8 + c0) = make_float2(g2, g3);
    }
}

// ---------------------------------------------------------------------------
extern "C" void kernel_launch(void* const* d_in, const int* in_sizes, int n_in,
                              void* d_out, int out_size) {
    const float *m = nullptr, *x = nullptr, *r = nullptr, *w = nullptr;
    for (int i = 0; i < n_in; ++i) {
        int s = in_sizes[i];
        if      (s == 33554432) m = (const float*)d_in[i];
        else if (s == 2097152)  x = (const float*)d_in[i];
        else if (s == 4)        r = (const float*)d_in[i];
        else if (s == 65536)    w = (const float*)d_in[i];
    }
    float* out = (float*)d_out;

    cudaFuncSetAttribute(k_mma, cudaFuncAttributeMaxDynamicSharedMemorySize, SMT);

    k_pre<<<256 + 8192, 256>>>(x, w, m);
    k_vt<<<512, 256>>>();
    k_mma<<<dim3(32, 4, 2), 256, SMT>>>(m, r, out);
}

// round 12
// speedup vs baseline: 2.0627x; 1.1628x over previous
#include <cuda_runtime.h>
#include <cuda_fp16.h>
#include <math.h>
#include <float.h>
#include <stdint.h>

#define NN 4096
#define HID 256
#define RANK0 1228

// k_mma dyn smem byte offsets
#define MOF 0u
#define MBS 18432u     // m buf: 128 x 36 floats
#define WHO 36864u
#define WBS 10240u     // w buf: 128 x 40 halves
#define WLO 57344u
#define VHO 77824u
#define VBS 5120u      // v buf: 64 x 40 halves
#define VLO 88064u
#define SMT 98304

__device__ __align__(128) float  g_value[2ull * NN * HID];   // (b, j, h*64+k)
__device__ float2 g_stats[2 * NN];
__device__ __align__(128) __half g_vhi[8ull * 64 * NN];      // (b*4+h, k, j)
__device__ __align__(128) __half g_vlo[8ull * 64 * NN];

__device__ __forceinline__ void cpa16(uint32_t dst, const void* src) {
    asm volatile("cp.async.cg.shared.global [%0], [%1], 16;" :: "r"(dst), "l"(src));
}
__device__ __forceinline__ uint32_t pk(__half a, __half b) {
    __half2 h = __halves2half2(a, b);
    return *(uint32_t*)&h;
}
#define LDSM4(r0, r1, r2, r3, a) \
    asm volatile("ldmatrix.sync.aligned.m8n8.x4.shared.b16 {%0,%1,%2,%3},[%4];" \
        : "=r"(r0), "=r"(r1), "=r"(r2), "=r"(r3) : "r"(a))
#define MMA(d, a0, a1, a2, a3, b0, b1) \
    asm volatile("mma.sync.aligned.m16n8k16.row.col.f32.f16.f16.f32 " \
        "{%0,%1,%2,%3},{%4,%5,%6,%7},{%8,%9},{%0,%1,%2,%3};" \
        : "+f"((d)[0]), "+f"((d)[1]), "+f"((d)[2]), "+f"((d)[3]) \
        : "r"(a0), "r"(a1), "r"(a2), "r"(a3), "r"(b0), "r"(b1))

// ---------------------------------------------------------------------------
// k_pre: blocks [0,256) -> g_value (verbatim) ; [256,8448) -> g_stats
// stats: single-pass 256-bin value histogram select (exact order statistics)
// ---------------------------------------------------------------------------
__global__ void __launch_bounds__(256) k_pre(const float* __restrict__ x,
                                             const float* __restrict__ wgt,
                                             const float* __restrict__ m) {
    __shared__ __align__(16) float u_sm[9248];
    const int t = threadIdx.x;
    if (blockIdx.x < 256) {
        float* wsh = u_sm;
        float* xsh = u_sm + 8192;
        const size_t base = (size_t)blockIdx.x * 32 * HID;
        const int jj = t >> 3, cg = t & 7;
        float4 acc[8];
#pragma unroll
        for (int q = 0; q < 8; ++q) acc[q] = make_float4(0.f, 0.f, 0.f, 0.f);
        for (int ct = 0; ct < 8; ++ct) {
            __syncthreads();
#pragma unroll
            for (int s = 0; s < 32; ++s) {
                int idx = t + 256 * s;
                int cc = idx >> 8, col = idx & 255;
                wsh[idx] = wgt[(col >> 6) * 16384 + (ct * 32 + cc) * 64 + (col & 63)];
            }
#pragma unroll
            for (int s = 0; s < 4; ++s) {
                int idx = t + 256 * s;
                int jr = idx >> 5, cc = idx & 31;
                xsh[jr * 33 + cc] = x[base + (size_t)jr * HID + ct * 32 + cc];
            }
            __syncthreads();
#pragma unroll 4
            for (int cc = 0; cc < 32; ++cc) {
                float xv = xsh[jj * 33 + cc];
#pragma unroll
                for (int qq = 0; qq < 8; ++qq) {
                    int qe = (qq + cg) & 7;
                    float4 wv = *(const float4*)(wsh + cc * 256 + cg * 32 + qe * 4);
                    acc[qq].x = fmaf(xv, wv.x, acc[qq].x);
                    acc[qq].y = fmaf(xv, wv.y, acc[qq].y);
                    acc[qq].z = fmaf(xv, wv.z, acc[qq].z);
                    acc[qq].w = fmaf(xv, wv.w, acc[qq].w);
                }
            }
        }
        float* orow = g_value + base + (size_t)jj * HID + cg * 32;
#pragma unroll
        for (int qq = 0; qq < 8; ++qq) {
            int qe = (qq + cg) & 7;
            *(float4*)(orow + qe * 4) = acc[qq];
        }
        return;
    }

    // ---- stats: histogram select ----
    const int row = blockIdx.x - 256;
    const float* p = m + (size_t)row * NN;
    float*    list = u_sm;                      // up to 1024 candidates
    unsigned* hist = (unsigned*)(u_sm + 1024);  // 256 bins
    __shared__ int s_clo, s_cnt, s_bina, s_binb, s_excla, s_fail;

    float4 vr[4];
#pragma unroll
    for (int s = 0; s < 4; ++s) vr[s] = *(const float4*)(p + 4 * (t + 256 * s));
    float fv[16];
#pragma unroll
    for (int s = 0; s < 4; ++s) {
        fv[s * 4 + 0] = vr[s].x; fv[s * 4 + 1] = vr[s].y;
        fv[s * 4 + 2] = vr[s].z; fv[s * 4 + 3] = vr[s].w;
    }

    bool done = false;
    for (int attempt = 0; attempt < 2 && !done; ++attempt) {
        const float lo    = attempt ? 0.f   : 0.26f;
        const float scale = attempt ? 256.f : 3200.f;
        __syncthreads();
        if (t == 0) { s_clo = 0; s_cnt = 0; s_fail = 0; }
        hist[t] = 0;
        __syncthreads();
        int my_lo = 0;
        int bins[16];
#pragma unroll
        for (int q = 0; q < 16; ++q) {
            float f = fv[q];
            int b;
            if (attempt == 0) {
                if (f < lo) { my_lo++; b = -1; }
                else { b = (int)((f - lo) * scale); if (b > 255) b = -1; }
            } else {
                b = (int)((f - lo) * scale);
                b = b < 0 ? 0 : (b > 255 ? 255 : b);
            }
            bins[q] = b;
            if (b >= 0) atomicAdd(&hist[b], 1u);
        }
        if (my_lo) atomicAdd((unsigned*)&s_clo, (unsigned)my_lo);
        __syncthreads();
        const int c_lo = s_clo;
        const unsigned hv = hist[t];
        for (int d = 1; d < 256; d <<= 1) {          // inclusive HS scan
            unsigned addv = (t >= d) ? hist[t - d] : 0u;
            __syncthreads();
            hist[t] += addv;
            __syncthreads();
        }
        const int want_a = RANK0 - c_lo;
        const int want_b = want_a + 1;
        const int total  = (int)hist[255];
        if (want_a < 0 || want_b >= total) continue;  // bracket miss (uniform across block)

        const int incl = (int)hist[t];
        const int excl = incl - (int)hv;
        if (excl <= want_a && want_a < incl) { s_bina = t; s_excla = excl; }
        if (excl <= want_b && want_b < incl) { s_binb = t; }
        __syncthreads();
        if (t == 0 && (int)hist[s_binb] - s_excla > 1024) s_fail = 1;
        __syncthreads();
        if (s_fail) continue;
        const int ba = s_bina, bb = s_binb;
#pragma unroll
        for (int q = 0; q < 16; ++q) {
            int b = bins[q];
            if (b >= ba && b <= bb) list[atomicAdd(&s_cnt, 1)] = fv[q];
        }
        __syncthreads();
        if (t == 0) {
            const int n = s_cnt;
            for (int a = 1; a < n; ++a) {            // insertion sort (ascending)
                float key = list[a];
                int bq = a - 1;
                while (bq >= 0 && list[bq] > key) { list[bq + 1] = list[bq]; --bq; }
                list[bq + 1] = key;
            }
            const int ia = want_a - s_excla;
            g_stats[row] = make_float2(list[ia], list[ia + 1]);
        }
        done = true;
    }
}

// ---------------------------------------------------------------------------
// k_vt: g_value (b,j,h*64+k) -> g_vhi/g_vlo (b*4+h, k, j) fp16 hi/lo split
// ---------------------------------------------------------------------------
__global__ void __launch_bounds__(256) k_vt() {
    __shared__ float ts[64][65];
    const int t = threadIdx.x;
    const int bh = blockIdx.x >> 6, jt = blockIdx.x & 63;
#pragma unroll
    for (int s = 0; s < 4; ++s) {
        int idx = t + 256 * s;
        int jj = idx >> 4, q = idx & 15;
        float4 v = *(const float4*)(g_value +
            ((size_t)(bh >> 2) * NN + jt * 64 + jj) * HID + (bh & 3) * 64 + q * 4);
        ts[jj][q * 4 + 0] = v.x; ts[jj][q * 4 + 1] = v.y;
        ts[jj][q * 4 + 2] = v.z; ts[jj][q * 4 + 3] = v.w;
    }
    __syncthreads();
    const int k = t >> 2, seg = t & 3;
    uint32_t uh[8], ul[8];
#pragma unroll
    for (int e = 0; e < 8; ++e) {
        float v0 = ts[seg * 16 + 2 * e][k], v1 = ts[seg * 16 + 2 * e + 1][k];
        __half h0 = __float2half_rn(v0), h1 = __float2half_rn(v1);
        uh[e] = pk(h0, h1);
        ul[e] = pk(__float2half_rn(v0 - __half2float(h0)),
                   __float2half_rn(v1 - __half2float(h1)));
    }
    size_t dst = ((size_t)(bh * 64 + k)) * NN + jt * 64 + seg * 16;
    *(uint4*)(g_vhi + dst)     = make_uint4(uh[0], uh[1], uh[2], uh[3]);
    *(uint4*)(g_vhi + dst + 8) = make_uint4(uh[4], uh[5], uh[6], uh[7]);
    *(uint4*)(g_vlo + dst)     = make_uint4(ul[0], ul[1], ul[2], ul[3]);
    *(uint4*)(g_vlo + dst + 8) = make_uint4(ul[4], ul[5], ul[6], ul[7]);
}

// ---------------------------------------------------------------------------
// k_mma: CTA = (128 i, h, b). j-tiles of 32; mma.sync m16n8k16 f16 hi/lo x3.
// (R10 verbatim)
// ---------------------------------------------------------------------------
__global__ void __launch_bounds__(256, 2) k_mma(const float* __restrict__ m,
                                                const float* __restrict__ r,
                                                float* __restrict__ out) {
    extern __shared__ __align__(16) char sgen[];
    __shared__ float thr_s[128];
    const int t = threadIdx.x, warp = t >> 5, lane = t & 31;
    const int h = blockIdx.y, bz = blockIdx.z;
    const int i_base = blockIdx.x * 128;
    const int bh64 = (bz * 4 + h) * 64;
    const uint32_t sb = (uint32_t)__cvta_generic_to_shared(sgen);

    const float rv = r[h], r2 = __fmul_rn(rv, rv);
    if (t < 128) {
        float2 st = g_stats[bz * NN + i_base + t];
        thr_s[t] = __fadd_rn(__fmul_rn(0.5f, __fmul_rn(r2, st.x)),
                             __fmul_rn(0.5f, __fmul_rn(r2, st.y)));
    }
    __syncthreads();

    const int i = t & 127, jh = t >> 7;
    const float* mbase = m + (size_t)(bz * NN + i_base) * NN;
    const float thr_i = thr_s[i];
    float den_acc = 0.f;
    float acc[32];
#pragma unroll
    for (int q = 0; q < 32; ++q) acc[q] = 0.f;

    {
#pragma unroll
        for (int s = 0; s < 4; ++s) {
            int idx = t + 256 * s;
            int i2 = idx >> 3, q = idx & 7;
            cpa16(sb + MOF + (unsigned)i2 * 144u + (unsigned)q * 16u,
                  mbase + (size_t)i2 * NN + q * 4);
        }
        int k2 = t >> 2, q = t & 3;
        cpa16(sb + VHO + (unsigned)k2 * 80u + (unsigned)q * 16u,
              g_vhi + (size_t)(bh64 + k2) * NN + q * 8);
        cpa16(sb + VLO + (unsigned)k2 * 80u + (unsigned)q * 16u,
              g_vlo + (size_t)(bh64 + k2) * NN + q * 8);
        asm volatile("cp.async.commit_group;");
    }

    for (int c = 0; c < 128; ++c) {
        const unsigned buf = (unsigned)(c & 1);
        if (c < 127) {
            const int j0n = (c + 1) * 32;
            const unsigned nb = (unsigned)((c + 1) & 1);
#pragma unroll
            for (int s = 0; s < 4; ++s) {
                int idx = t + 256 * s;
                int i2 = idx >> 3, q = idx & 7;
                cpa16(sb + MOF + nb * MBS + (unsigned)i2 * 144u + (unsigned)q * 16u,
                      mbase + (size_t)i2 * NN + j0n + q * 4);
            }
            int k2 = t >> 2, q = t & 3;
            cpa16(sb + VHO + nb * VBS + (unsigned)k2 * 80u + (unsigned)q * 16u,
                  g_vhi + (size_t)(bh64 + k2) * NN + j0n + q * 8);
            cpa16(sb + VLO + nb * VBS + (unsigned)k2 * 80u + (unsigned)q * 16u,
                  g_vlo + (size_t)(bh64 + k2) * NN + j0n + q * 8);
            asm volatile("cp.async.commit_group;");
            asm volatile("cp.async.wait_group 1;");
        } else {
            asm volatile("cp.async.wait_group 0;");
        }
        __syncthreads();

        {
            const float* ms = (const float*)(sgen + MOF + buf * MBS) + i * 36 + jh * 16;
            float w[16];
#pragma unroll
            for (int q = 0; q < 4; ++q) {
                float4 mv = *(const float4*)(ms + q * 4);
                float s0 = __fmul_rn(mv.x, r2), s1 = __fmul_rn(mv.y, r2);
                float s2 = __fmul_rn(mv.z, r2), s3 = __fmul_rn(mv.w, r2);
                w[q * 4 + 0] = (s0 <= thr_i) ? __expf(-s0) : 0.f;
                w[q * 4 + 1] = (s1 <= thr_i) ? __expf(-s1) : 0.f;
                w[q * 4 + 2] = (s2 <= thr_i) ? __expf(-s2) : 0.f;
                w[q * 4 + 3] = (s3 <= thr_i) ? __expf(-s3) : 0.f;
            }
#pragma unroll
            for (int q = 0; q < 16; ++q) den_acc += w[q];
            uint32_t uh[8], ul[8];
#pragma unroll
            for (int e = 0; e < 8; ++e) {
                __half h0 = __float2half_rn(w[2 * e]), h1 = __float2half_rn(w[2 * e + 1]);
                uh[e] = pk(h0, h1);
                ul[e] = pk(__float2half_rn(w[2 * e] - __half2float(h0)),
                           __float2half_rn(w[2 * e + 1] - __half2float(h1)));
            }
            char* wd = sgen + WHO + buf * WBS + i * 80 + jh * 32;
            *(uint4*)wd        = make_uint4(uh[0], uh[1], uh[2], uh[3]);
            *(uint4*)(wd + 16) = make_uint4(uh[4], uh[5], uh[6], uh[7]);
            char* ld = wd + (WLO - WHO);
            *(uint4*)ld        = make_uint4(ul[0], ul[1], ul[2], ul[3]);
            *(uint4*)(ld + 16) = make_uint4(ul[4], ul[5], ul[6], ul[7]);
        }
        __syncthreads();

        {
            const int i0 = warp * 16;
            const unsigned arow = (unsigned)(i0 + (lane & 15)) * 80u +
                                  (unsigned)((lane >> 4) << 4);
            const int nb_ = (lane & 7) + ((lane >> 4) << 3);
            const unsigned brow0 = (unsigned)nb_ * 80u + (unsigned)((lane & 8) << 1);
#pragma unroll
            for (int cc = 0; cc < 2; ++cc) {
                uint32_t ah0, ah1, ah2, ah3, al0, al1, al2, al3;
                uint32_t aaddr = sb + WHO + buf * WBS + arow + (unsigned)cc * 32u;
                LDSM4(ah0, ah1, ah2, ah3, aaddr);
                LDSM4(al0, al1, al2, al3, aaddr + (WLO - WHO));
#pragma unroll
                for (int g = 0; g < 4; ++g) {
                    uint32_t bh0, bh1, bh2, bh3, bl0, bl1, bl2, bl3;
                    uint32_t baddr = sb + VHO + buf * VBS + brow0 +
                                     (unsigned)(g * 16) * 80u + (unsigned)cc * 32u;
                    LDSM4(bh0, bh1, bh2, bh3, baddr);
                    LDSM4(bl0, bl1, bl2, bl3, baddr + (VLO - VHO));
                    float* d0 = acc + g * 8;
                    float* d1 = acc + g * 8 + 4;
                    MMA(d0, ah0, ah1, ah2, ah3, bh0, bh1);
                    MMA(d0, ah0, ah1, ah2, ah3, bl0, bl1);
                    MMA(d0, al0, al1, al2, al3, bh0, bh1);
                    MMA(d1, ah0, ah1, ah2, ah3, bh2, bh3);
                    MMA(d1, ah0, ah1, ah2, ah3, bl2, bl3);
                    MMA(d1, al0, al1, al2, al3, bh2, bh3);
                }
            }
        }
        __syncthreads();
    }

    float* sden = (float*)sgen;
    sden[t] = den_acc;
    __syncthreads();
    if (t < 128) sden[256 + t] = sden[t] + sden[t + 128];
    __syncthreads();
    const float* dden = sden + 256;
    const int i0 = warp * 16;
    const int r0 = lane >> 2, c0 = (lane & 3) * 2;
    const float inv0 = 1.0f / dden[i0 + r0];
    const float inv1 = 1.0f / dden[i0 + r0 + 8];
    float* ob = out + ((size_t)(bz * NN + i_base + i0)) * HID + h * 64;
#pragma unroll
    for (int nt = 0; nt < 8; ++nt) {
        float v0 = acc[nt * 4 + 0] * inv0, v1 = acc[nt * 4 + 1] * inv0;
        float v2 = acc[nt * 4 + 2] * inv1, v3 = acc[nt * 4 + 3] * inv1;
        float g0 = 0.5f * v0 * (1.0f + erff(v0 * 0.7071067811865475f));
        float g1 = 0.5f * v1 * (1.0f + erff(v1 * 0.7071067811865475f));
        float g2 = 0.5f * v2 * (1.0f + erff(v2 * 0.7071067811865475f));
        float g3 = 0.5f * v3 * (1.0f + erff(v3 * 0.7071067811865475f));
        *(float2*)(ob + (size_t)r0 * HID + nt * 8 + c0)       = make_float2(g0, g1);
        *(float2*)(ob + (size_t)(r0 + 8) * HID + nt * 8 + c0) = make_float2(g2, g3);
    }
}

// ---------------------------------------------------------------------------
extern "C" void kernel_launch(void* const* d_in, const int* in_sizes, int n_in,
                              void* d_out, int out_size) {
    const float *m = nullptr, *x = nullptr, *r = nullptr, *w = nullptr;
    for (int i = 0; i < n_in; ++i) {
        int s = in_sizes[i];
        if      (s == 33554432) m = (const float*)d_in[i];
        else if (s == 2097152)  x = (const float*)d_in[i];
        else if (s == 4)        r = (const float*)d_in[i];
        else if (s == 65536)    w = (const float*)d_in[i];
    }
    float* out = (float*)d_out;

    cudaFuncSetAttribute(k_mma, cudaFuncAttributeMaxDynamicSharedMemorySize, SMT);

    k_pre<<<256 + 8192, 256>>>(x, w, m);
    k_vt<<<512, 256>>>();
    k_mma<<<dim3(32, 4, 2), 256, SMT>>>(m, r, out);
}

// round 13
// speedup vs baseline: 2.1636x; 1.0489x over previous
#include <cuda_runtime.h>
#include <cuda_fp16.h>
#include <math.h>
#include <float.h>
#include <stdint.h>

#define NN 4096
#define HID 256
#define RANK0 1228

// k_mma dyn smem byte offsets
#define MOF 0u
#define MBS 18432u     // m buf: 128 x 36 floats
#define WHO 36864u
#define WBS 10240u     // w buf: 128 x 40 halves
#define WLO 57344u
#define VHO 77824u
#define VBS 5120u      // v buf: 64 x 40 halves
#define VLO 88064u
#define SMT 98304

__device__ __align__(128) float  g_value[2ull * NN * HID];   // (b, j, h*64+k)
__device__ float2 g_stats[2 * NN];
__device__ __align__(128) __half g_vhi[8ull * 64 * NN];      // (b*4+h, k, j)
__device__ __align__(128) __half g_vlo[8ull * 64 * NN];

__device__ __forceinline__ void cpa16(uint32_t dst, const void* src) {
    asm volatile("cp.async.cg.shared.global [%0], [%1], 16;" :: "r"(dst), "l"(src));
}
__device__ __forceinline__ uint32_t pk(__half a, __half b) {
    __half2 h = __halves2half2(a, b);
    return *(uint32_t*)&h;
}
// monotone bin classification; must be used identically in both passes
__device__ __forceinline__ int binof(float f, int attempt) {
    if (attempt == 0) {
        if (f < 0.26f) return -2;                    // below window
        int b = (int)((f - 0.26f) * 3200.f);
        return (b > 255) ? -1 : b;                   // above window
    }
    int b = (int)(f * 256.f);
    return b < 0 ? 0 : (b > 255 ? 255 : b);
}
#define LDSM4(r0, r1, r2, r3, a) \
    asm volatile("ldmatrix.sync.aligned.m8n8.x4.shared.b16 {%0,%1,%2,%3},[%4];" \
        : "=r"(r0), "=r"(r1), "=r"(r2), "=r"(r3) : "r"(a))
#define MMA(d, a0, a1, a2, a3, b0, b1) \
    asm volatile("mma.sync.aligned.m16n8k16.row.col.f32.f16.f16.f32 " \
        "{%0,%1,%2,%3},{%4,%5,%6,%7},{%8,%9},{%0,%1,%2,%3};" \
        : "+f"((d)[0]), "+f"((d)[1]), "+f"((d)[2]), "+f"((d)[3]) \
        : "r"(a0), "r"(a1), "r"(a2), "r"(a3), "r"(b0), "r"(b1))

// ---------------------------------------------------------------------------
// k_pre: blocks [0,256) -> g_value ; [256,8448) -> g_stats (histogram select,
// warp-shuffle scan, bins recomputed in gather)
// ---------------------------------------------------------------------------
__global__ void __launch_bounds__(256, 3) k_pre(const float* __restrict__ x,
                                                const float* __restrict__ wgt,
                                                const float* __restrict__ m) {
    __shared__ __align__(16) float u_sm[9248];
    const int t = threadIdx.x;
    if (blockIdx.x < 256) {
        float* wsh = u_sm;
        float* xsh = u_sm + 8192;
        const size_t base = (size_t)blockIdx.x * 32 * HID;
        const int jj = t >> 3, cg = t & 7;
        float4 acc[8];
#pragma unroll
        for (int q = 0; q < 8; ++q) acc[q] = make_float4(0.f, 0.f, 0.f, 0.f);
        for (int ct = 0; ct < 8; ++ct) {
            __syncthreads();
#pragma unroll
            for (int s = 0; s < 32; ++s) {
                int idx = t + 256 * s;
                int cc = idx >> 8, col = idx & 255;
                wsh[idx] = wgt[(col >> 6) * 16384 + (ct * 32 + cc) * 64 + (col & 63)];
            }
#pragma unroll
            for (int s = 0; s < 4; ++s) {
                int idx = t + 256 * s;
                int jr = idx >> 5, cc = idx & 31;
                xsh[jr * 33 + cc] = x[base + (size_t)jr * HID + ct * 32 + cc];
            }
            __syncthreads();
#pragma unroll 4
            for (int cc = 0; cc < 32; ++cc) {
                float xv = xsh[jj * 33 + cc];
#pragma unroll
                for (int qq = 0; qq < 8; ++qq) {
                    int qe = (qq + cg) & 7;
                    float4 wv = *(const float4*)(wsh + cc * 256 + cg * 32 + qe * 4);
                    acc[qq].x = fmaf(xv, wv.x, acc[qq].x);
                    acc[qq].y = fmaf(xv, wv.y, acc[qq].y);
                    acc[qq].z = fmaf(xv, wv.z, acc[qq].z);
                    acc[qq].w = fmaf(xv, wv.w, acc[qq].w);
                }
            }
        }
        float* orow = g_value + base + (size_t)jj * HID + cg * 32;
#pragma unroll
        for (int qq = 0; qq < 8; ++qq) {
            int qe = (qq + cg) & 7;
            *(float4*)(orow + qe * 4) = acc[qq];
        }
        return;
    }

    // ---- stats: histogram select ----
    const int row = blockIdx.x - 256;
    const float* p = m + (size_t)row * NN;
    float*    list = u_sm;                      // candidates
    unsigned* hist = (unsigned*)(u_sm + 1024);  // 256 bins
    __shared__ unsigned wsum[8];
    __shared__ int s_clo, s_cnt, s_bina, s_binb, s_excla, s_fail;
    const int lane = t & 31, wid = t >> 5;

    float4 vr[4];
#pragma unroll
    for (int s = 0; s < 4; ++s) vr[s] = *(const float4*)(p + 4 * (t + 256 * s));
    float fv[16];
#pragma unroll
    for (int s = 0; s < 4; ++s) {
        fv[s * 4 + 0] = vr[s].x; fv[s * 4 + 1] = vr[s].y;
        fv[s * 4 + 2] = vr[s].z; fv[s * 4 + 3] = vr[s].w;
    }

    bool done = false;
    for (int attempt = 0; attempt < 2 && !done; ++attempt) {
        __syncthreads();
        if (t == 0) { s_clo = 0; s_cnt = 0; s_fail = 0; }
        hist[t] = 0;
        __syncthreads();
        int my_lo = 0;
#pragma unroll
        for (int q = 0; q < 16; ++q) {
            int b = binof(fv[q], attempt);
            if (b == -2) my_lo++;
            else if (b >= 0) atomicAdd(&hist[b], 1u);
        }
        if (my_lo) atomicAdd((unsigned*)&s_clo, (unsigned)my_lo);
        __syncthreads();
        const int c_lo = s_clo;
        const unsigned hv = hist[t];

        // inclusive scan: warp shfl + warp-total scan
        unsigned v = hv;
#pragma unroll
        for (int d = 1; d < 32; d <<= 1) {
            unsigned nb = __shfl_up_sync(0xffffffffu, v, d);
            if (lane >= d) v += nb;
        }
        if (lane == 31) wsum[wid] = v;
        __syncthreads();
        if (t < 8) {
            unsigned xsc = wsum[t];
#pragma unroll
            for (int d = 1; d < 8; d <<= 1) {
                unsigned nb = __shfl_up_sync(0x000000ffu, xsc, d);
                if (t >= d) xsc += nb;
            }
            wsum[t] = xsc;
        }
        __syncthreads();
        const unsigned off = (wid > 0) ? wsum[wid - 1] : 0u;
        const int incl = (int)(v + off);
        const int excl = incl - (int)hv;
        const int total = (int)wsum[7];

        const int want_a = RANK0 - c_lo;
        const int want_b = want_a + 1;
        if (want_a < 0 || want_b >= total) continue;   // bracket miss

        if (excl <= want_a && want_a < incl) { s_bina = t; s_excla = excl; }
        if (excl <= want_b && want_b < incl) { s_binb = t; }
        __syncthreads();
        if (t == s_binb && incl - s_excla > 1024) s_fail = 1;
        __syncthreads();
        if (s_fail) continue;
        const int ba = s_bina, bb = s_binb;
#pragma unroll
        for (int q = 0; q < 16; ++q) {
            int b = binof(fv[q], attempt);
            if (b >= ba && b <= bb) list[atomicAdd(&s_cnt, 1)] = fv[q];
        }
        __syncthreads();
        if (t == 0) {
            const int n = s_cnt;
            for (int a = 1; a < n; ++a) {
                float key = list[a];
                int bq = a - 1;
                while (bq >= 0 && list[bq] > key) { list[bq + 1] = list[bq]; --bq; }
                list[bq + 1] = key;
            }
            const int ia = want_a - s_excla;
            g_stats[row] = make_float2(list[ia], list[ia + 1]);
        }
        done = true;
    }
}

// ---------------------------------------------------------------------------
// k_vt: g_value (b,j,h*64+k) -> g_vhi/g_vlo (b*4+h, k, j)  (verbatim)
// ---------------------------------------------------------------------------
__global__ void __launch_bounds__(256) k_vt() {
    __shared__ float ts[64][65];
    const int t = threadIdx.x;
    const int bh = blockIdx.x >> 6, jt = blockIdx.x & 63;
#pragma unroll
    for (int s = 0; s < 4; ++s) {
        int idx = t + 256 * s;
        int jj = idx >> 4, q = idx & 15;
        float4 v = *(const float4*)(g_value +
            ((size_t)(bh >> 2) * NN + jt * 64 + jj) * HID + (bh & 3) * 64 + q * 4);
        ts[jj][q * 4 + 0] = v.x; ts[jj][q * 4 + 1] = v.y;
        ts[jj][q * 4 + 2] = v.z; ts[jj][q * 4 + 3] = v.w;
    }
    __syncthreads();
    const int k = t >> 2, seg = t & 3;
    uint32_t uh[8], ul[8];
#pragma unroll
    for (int e = 0; e < 8; ++e) {
        float v0 = ts[seg * 16 + 2 * e][k], v1 = ts[seg * 16 + 2 * e + 1][k];
        __half h0 = __float2half_rn(v0), h1 = __float2half_rn(v1);
        uh[e] = pk(h0, h1);
        ul[e] = pk(__float2half_rn(v0 - __half2float(h0)),
                   __float2half_rn(v1 - __half2float(h1)));
    }
    size_t dst = ((size_t)(bh * 64 + k)) * NN + jt * 64 + seg * 16;
    *(uint4*)(g_vhi + dst)     = make_uint4(uh[0], uh[1], uh[2], uh[3]);
    *(uint4*)(g_vhi + dst + 8) = make_uint4(uh[4], uh[5], uh[6], uh[7]);
    *(uint4*)(g_vlo + dst)     = make_uint4(ul[0], ul[1], ul[2], ul[3]);
    *(uint4*)(g_vlo + dst + 8) = make_uint4(ul[4], ul[5], ul[6], ul[7]);
}

// ---------------------------------------------------------------------------
// k_mma: CTA = (128 i, h, b). j-tiles of 32; mma.sync m16n8k16 f16 hi/lo x3.
// (verbatim)
// ---------------------------------------------------------------------------
__global__ void __launch_bounds__(256, 2) k_mma(const float* __restrict__ m,
                                                const float* __restrict__ r,
                                                float* __restrict__ out) {
    extern __shared__ __align__(16) char sgen[];
    __shared__ float thr_s[128];
    const int t = threadIdx.x, warp = t >> 5, lane = t & 31;
    const int h = blockIdx.y, bz = blockIdx.z;
    const int i_base = blockIdx.x * 128;
    const int bh64 = (bz * 4 + h) * 64;
    const uint32_t sb = (uint32_t)__cvta_generic_to_shared(sgen);

    const float rv = r[h], r2 = __fmul_rn(rv, rv);
    if (t < 128) {
        float2 st = g_stats[bz * NN + i_base + t];
        thr_s[t] = __fadd_rn(__fmul_rn(0.5f, __fmul_rn(r2, st.x)),
                             __fmul_rn(0.5f, __fmul_rn(r2, st.y)));
    }
    __syncthreads();

    const int i = t & 127, jh = t >> 7;
    const float* mbase = m + (size_t)(bz * NN + i_base) * NN;
    const float thr_i = thr_s[i];
    float den_acc = 0.f;
    float acc[32];
#pragma unroll
    for (int q = 0; q < 32; ++q) acc[q] = 0.f;

    {
#pragma unroll
        for (int s = 0; s < 4; ++s) {
            int idx = t + 256 * s;
            int i2 = idx >> 3, q = idx & 7;
            cpa16(sb + MOF + (unsigned)i2 * 144u + (unsigned)q * 16u,
                  mbase + (size_t)i2 * NN + q * 4);
        }
        int k2 = t >> 2, q = t & 3;
        cpa16(sb + VHO + (unsigned)k2 * 80u + (unsigned)q * 16u,
              g_vhi + (size_t)(bh64 + k2) * NN + q * 8);
        cpa16(sb + VLO + (unsigned)k2 * 80u + (unsigned)q * 16u,
              g_vlo + (size_t)(bh64 + k2) * NN + q * 8);
        asm volatile("cp.async.commit_group;");
    }

    for (int c = 0; c < 128; ++c) {
        const unsigned buf = (unsigned)(c & 1);
        if (c < 127) {
            const int j0n = (c + 1) * 32;
            const unsigned nb = (unsigned)((c + 1) & 1);
#pragma unroll
            for (int s = 0; s < 4; ++s) {
                int idx = t + 256 * s;
                int i2 = idx >> 3, q = idx & 7;
                cpa16(sb + MOF + nb * MBS + (unsigned)i2 * 144u + (unsigned)q * 16u,
                      mbase + (size_t)i2 * NN + j0n + q * 4);
            }
            int k2 = t >> 2, q = t & 3;
            cpa16(sb + VHO + nb * VBS + (unsigned)k2 * 80u + (unsigned)q * 16u,
                  g_vhi + (size_t)(bh64 + k2) * NN + j0n + q * 8);
            cpa16(sb + VLO + nb * VBS + (unsigned)k2 * 80u + (unsigned)q * 16u,
                  g_vlo + (size_t)(bh64 + k2) * NN + j0n + q * 8);
            asm volatile("cp.async.commit_group;");
            asm volatile("cp.async.wait_group 1;");
        } else {
            asm volatile("cp.async.wait_group 0;");
        }
        __syncthreads();

        {
            const float* ms = (const float*)(sgen + MOF + buf * MBS) + i * 36 + jh * 16;
            float w[16];
#pragma unroll
            for (int q = 0; q < 4; ++q) {
                float4 mv = *(const float4*)(ms + q * 4);
                float s0 = __fmul_rn(mv.x, r2), s1 = __fmul_rn(mv.y, r2);
                float s2 = __fmul_rn(mv.z, r2), s3 = __fmul_rn(mv.w, r2);
                w[q * 4 + 0] = (s0 <= thr_i) ? __expf(-s0) : 0.f;
                w[q * 4 + 1] = (s1 <= thr_i) ? __expf(-s1) : 0.f;
                w[q * 4 + 2] = (s2 <= thr_i) ? __expf(-s2) : 0.f;
                w[q * 4 + 3] = (s3 <= thr_i) ? __expf(-s3) : 0.f;
            }
#pragma unroll
            for (int q = 0; q < 16; ++q) den_acc += w[q];
            uint32_t uh[8], ul[8];
#pragma unroll
            for (int e = 0; e < 8; ++e) {
                __half h0 = __float2half_rn(w[2 * e]), h1 = __float2half_rn(w[2 * e + 1]);
                uh[e] = pk(h0, h1);
                ul[e] = pk(__float2half_rn(w[2 * e] - __half2float(h0)),
                           __float2half_rn(w[2 * e + 1] - __half2float(h1)));
            }
            char* wd = sgen + WHO + buf * WBS + i * 80 + jh * 32;
            *(uint4*)wd        = make_uint4(uh[0], uh[1], uh[2], uh[3]);
            *(uint4*)(wd + 16) = make_uint4(uh[4], uh[5], uh[6], uh[7]);
            char* ld = wd + (WLO - WHO);
            *(uint4*)ld        = make_uint4(ul[0], ul[1], ul[2], ul[3]);
            *(uint4*)(ld + 16) = make_uint4(ul[4], ul[5], ul[6], ul[7]);
        }
        __syncthreads();

        {
            const int i0 = warp * 16;
            const unsigned arow = (unsigned)(i0 + (lane & 15)) * 80u +
                                  (unsigned)((lane >> 4) << 4);
            const int nb_ = (lane & 7) + ((lane >> 4) << 3);
            const unsigned brow0 = (unsigned)nb_ * 80u + (unsigned)((lane & 8) << 1);
#pragma unroll
            for (int cc = 0; cc < 2; ++cc) {
                uint32_t ah0, ah1, ah2, ah3, al0, al1, al2, al3;
                uint32_t aaddr = sb + WHO + buf * WBS + arow + (unsigned)cc * 32u;
                LDSM4(ah0, ah1, ah2, ah3, aaddr);
                LDSM4(al0, al1, al2, al3, aaddr + (WLO - WHO));
#pragma unroll
                for (int g = 0; g < 4; ++g) {
                    uint32_t bh0, bh1, bh2, bh3, bl0, bl1, bl2, bl3;
                    uint32_t baddr = sb + VHO + buf * VBS + brow0 +
                                     (unsigned)(g * 16) * 80u + (unsigned)cc * 32u;
                    LDSM4(bh0, bh1, bh2, bh3, baddr);
                    LDSM4(bl0, bl1, bl2, bl3, baddr + (VLO - VHO));
                    float* d0 = acc + g * 8;
                    float* d1 = acc + g * 8 + 4;
                    MMA(d0, ah0, ah1, ah2, ah3, bh0, bh1);
                    MMA(d0, ah0, ah1, ah2, ah3, bl0, bl1);
                    MMA(d0, al0, al1, al2, al3, bh0, bh1);
                    MMA(d1, ah0, ah1, ah2, ah3, bh2, bh3);
                    MMA(d1, ah0, ah1, ah2, ah3, bl2, bl3);
                    MMA(d1, al0, al1, al2, al3, bh2, bh3);
                }
            }
        }
        __syncthreads();
    }

    float* sden = (float*)sgen;
    sden[t] = den_acc;
    __syncthreads();
    if (t < 128) sden[256 + t] = sden[t] + sden[t + 128];
    __syncthreads();
    const float* dden = sden + 256;
    const int i0 = warp * 16;
    const int r0 = lane >> 2, c0 = (lane & 3) * 2;
    const float inv0 = 1.0f / dden[i0 + r0];
    const float inv1 = 1.0f / dden[i0 + r0 + 8];
    float* ob = out + ((size_t)(bz * NN + i_base + i0)) * HID + h * 64;
#pragma unroll
    for (int nt = 0; nt < 8; ++nt) {
        float v0 = acc[nt * 4 + 0] * inv0, v1 = acc[nt * 4 + 1] * inv0;
        float v2 = acc[nt * 4 + 2] * inv1, v3 = acc[nt * 4 + 3] * inv1;
        float g0 = 0.5f * v0 * (1.0f + erff(v0 * 0.7071067811865475f));
        float g1 = 0.5f * v1 * (1.0f + erff(v1 * 0.7071067811865475f));
        float g2 = 0.5f * v2 * (1.0f + erff(v2 * 0.7071067811865475f));
        float g3 = 0.5f * v3 * (1.0f + erff(v3 * 0.7071067811865475f));
        *(float2*)(ob + (size_t)r0 * HID + nt * 8 + c0)       = make_float2(g0, g1);
        *(float2*)(ob + (size_t)(r0 + 8) * HID + nt * 8 + c0) = make_float2(g2, g3);
    }
}

// ---------------------------------------------------------------------------
extern "C" void kernel_launch(void* const* d_in, const int* in_sizes, int n_in,
                              void* d_out, int out_size) {
    const float *m = nullptr, *x = nullptr, *r = nullptr, *w = nullptr;
    for (int i = 0; i < n_in; ++i) {
        int s = in_sizes[i];
        if      (s == 33554432) m = (const float*)d_in[i];
        else if (s == 2097152)  x = (const float*)d_in[i];
        else if (s == 4)        r = (const float*)d_in[i];
        else if (s == 65536)    w = (const float*)d_in[i];
    }
    float* out = (float*)d_out;

    cudaFuncSetAttribute(k_mma, cudaFuncAttributeMaxDynamicSharedMemorySize, SMT);

    k_pre<<<256 + 8192, 256>>>(x, w, m);
    k_vt<<<512, 256>>>();
    k_mma<<<dim3(32, 4, 2), 256, SMT>>>(m, r, out);
}

// round 14
// speedup vs baseline: 2.2504x; 1.0401x over previous
#include <cuda_runtime.h>
#include <cuda_fp16.h>
#include <math.h>
#include <float.h>
#include <stdint.h>

#define NN 4096
#define HID 256
#define RANK0 1228

// k_mma dyn smem byte offsets
#define MOF 0u
#define MBS 18432u     // m buf: 128 x 36 floats
#define WHO 36864u
#define WBS 10240u     // w-hi buf: 128 x 40 halves
#define VHO 57344u
#define VBS 5120u      // v buf: 64 x 40 halves
#define VLO 67584u
#define SMT 77824

__device__ __align__(128) float  g_value[2ull * NN * HID];   // (b, j, h*64+k)
__device__ float2 g_stats[2 * NN];
__device__ __align__(128) __half g_vhi[8ull * 64 * NN];      // (b*4+h, k, j)
__device__ __align__(128) __half g_vlo[8ull * 64 * NN];

__device__ __forceinline__ void cpa16(uint32_t dst, const void* src) {
    asm volatile("cp.async.cg.shared.global [%0], [%1], 16;" :: "r"(dst), "l"(src));
}
__device__ __forceinline__ uint32_t pk(__half a, __half b) {
    __half2 h = __halves2half2(a, b);
    return *(uint32_t*)&h;
}
// monotone bin classification; used identically in both passes
__device__ __forceinline__ int binof(float f, int attempt) {
    if (attempt == 0) {
        if (f < 0.26f) return -2;
        int b = (int)((f - 0.26f) * 3200.f);
        return (b > 255) ? -1 : b;
    }
    int b = (int)(f * 256.f);
    return b < 0 ? 0 : (b > 255 ? 255 : b);
}
#define LDSM4(r0, r1, r2, r3, a) \
    asm volatile("ldmatrix.sync.aligned.m8n8.x4.shared.b16 {%0,%1,%2,%3},[%4];" \
        : "=r"(r0), "=r"(r1), "=r"(r2), "=r"(r3) : "r"(a))
#define MMA(d, a0, a1, a2, a3, b0, b1) \
    asm volatile("mma.sync.aligned.m16n8k16.row.col.f32.f16.f16.f32 " \
        "{%0,%1,%2,%3},{%4,%5,%6,%7},{%8,%9},{%0,%1,%2,%3};" \
        : "+f"((d)[0]), "+f"((d)[1]), "+f"((d)[2]), "+f"((d)[3]) \
        : "r"(a0), "r"(a1), "r"(a2), "r"(a3), "r"(b0), "r"(b1))

// ---------------------------------------------------------------------------
// k_pre: blocks [0,256) -> g_value ; [256,8448) -> g_stats  (R12 verbatim)
// ---------------------------------------------------------------------------
__global__ void __launch_bounds__(256, 3) k_pre(const float* __restrict__ x,
                                                const float* __restrict__ wgt,
                                                const float* __restrict__ m) {
    __shared__ __align__(16) float u_sm[9248];
    const int t = threadIdx.x;
    if (blockIdx.x < 256) {
        float* wsh = u_sm;
        float* xsh = u_sm + 8192;
        const size_t base = (size_t)blockIdx.x * 32 * HID;
        const int jj = t >> 3, cg = t & 7;
        float4 acc[8];
#pragma unroll
        for (int q = 0; q < 8; ++q) acc[q] = make_float4(0.f, 0.f, 0.f, 0.f);
        for (int ct = 0; ct < 8; ++ct) {
            __syncthreads();
#pragma unroll
            for (int s = 0; s < 32; ++s) {
                int idx = t + 256 * s;
                int cc = idx >> 8, col = idx & 255;
                wsh[idx] = wgt[(col >> 6) * 16384 + (ct * 32 + cc) * 64 + (col & 63)];
            }
#pragma unroll
            for (int s = 0; s < 4; ++s) {
                int idx = t + 256 * s;
                int jr = idx >> 5, cc = idx & 31;
                xsh[jr * 33 + cc] = x[base + (size_t)jr * HID + ct * 32 + cc];
            }
            __syncthreads();
#pragma unroll 4
            for (int cc = 0; cc < 32; ++cc) {
                float xv = xsh[jj * 33 + cc];
#pragma unroll
                for (int qq = 0; qq < 8; ++qq) {
                    int qe = (qq + cg) & 7;
                    float4 wv = *(const float4*)(wsh + cc * 256 + cg * 32 + qe * 4);
                    acc[qq].x = fmaf(xv, wv.x, acc[qq].x);
                    acc[qq].y = fmaf(xv, wv.y, acc[qq].y);
                    acc[qq].z = fmaf(xv, wv.z, acc[qq].z);
                    acc[qq].w = fmaf(xv, wv.w, acc[qq].w);
                }
            }
        }
        float* orow = g_value + base + (size_t)jj * HID + cg * 32;
#pragma unroll
        for (int qq = 0; qq < 8; ++qq) {
            int qe = (qq + cg) & 7;
            *(float4*)(orow + qe * 4) = acc[qq];
        }
        return;
    }

    const int row = blockIdx.x - 256;
    const float* p = m + (size_t)row * NN;
    float*    list = u_sm;
    unsigned* hist = (unsigned*)(u_sm + 1024);
    __shared__ unsigned wsum[8];
    __shared__ int s_clo, s_cnt, s_bina, s_binb, s_excla, s_fail;
    const int lane = t & 31, wid = t >> 5;

    float4 vr[4];
#pragma unroll
    for (int s = 0; s < 4; ++s) vr[s] = *(const float4*)(p + 4 * (t + 256 * s));
    float fv[16];
#pragma unroll
    for (int s = 0; s < 4; ++s) {
        fv[s * 4 + 0] = vr[s].x; fv[s * 4 + 1] = vr[s].y;
        fv[s * 4 + 2] = vr[s].z; fv[s * 4 + 3] = vr[s].w;
    }

    bool done = false;
    for (int attempt = 0; attempt < 2 && !done; ++attempt) {
        __syncthreads();
        if (t == 0) { s_clo = 0; s_cnt = 0; s_fail = 0; }
        hist[t] = 0;
        __syncthreads();
        int my_lo = 0;
#pragma unroll
        for (int q = 0; q < 16; ++q) {
            int b = binof(fv[q], attempt);
            if (b == -2) my_lo++;
            else if (b >= 0) atomicAdd(&hist[b], 1u);
        }
        if (my_lo) atomicAdd((unsigned*)&s_clo, (unsigned)my_lo);
        __syncthreads();
        const int c_lo = s_clo;
        const unsigned hv = hist[t];

        unsigned v = hv;
#pragma unroll
        for (int d = 1; d < 32; d <<= 1) {
            unsigned nb = __shfl_up_sync(0xffffffffu, v, d);
            if (lane >= d) v += nb;
        }
        if (lane == 31) wsum[wid] = v;
        __syncthreads();
        if (t < 8) {
            unsigned xsc = wsum[t];
#pragma unroll
            for (int d = 1; d < 8; d <<= 1) {
                unsigned nb = __shfl_up_sync(0x000000ffu, xsc, d);
                if (t >= d) xsc += nb;
            }
            wsum[t] = xsc;
        }
        __syncthreads();
        const unsigned off = (wid > 0) ? wsum[wid - 1] : 0u;
        const int incl = (int)(v + off);
        const int excl = incl - (int)hv;
        const int total = (int)wsum[7];

        const int want_a = RANK0 - c_lo;
        const int want_b = want_a + 1;
        if (want_a < 0 || want_b >= total) continue;

        if (excl <= want_a && want_a < incl) { s_bina = t; s_excla = excl; }
        if (excl <= want_b && want_b < incl) { s_binb = t; }
        __syncthreads();
        if (t == s_binb && incl - s_excla > 1024) s_fail = 1;
        __syncthreads();
        if (s_fail) continue;
        const int ba = s_bina, bb = s_binb;
#pragma unroll
        for (int q = 0; q < 16; ++q) {
            int b = binof(fv[q], attempt);
            if (b >= ba && b <= bb) list[atomicAdd(&s_cnt, 1)] = fv[q];
        }
        __syncthreads();
        if (t == 0) {
            const int n = s_cnt;
            for (int a = 1; a < n; ++a) {
                float key = list[a];
                int bq = a - 1;
                while (bq >= 0 && list[bq] > key) { list[bq + 1] = list[bq]; --bq; }
                list[bq + 1] = key;
            }
            const int ia = want_a - s_excla;
            g_stats[row] = make_float2(list[ia], list[ia + 1]);
        }
        done = true;
    }
}

// ---------------------------------------------------------------------------
// k_vt: g_value (b,j,h*64+k) -> g_vhi/g_vlo (b*4+h, k, j)  (verbatim)
// ---------------------------------------------------------------------------
__global__ void __launch_bounds__(256) k_vt() {
    __shared__ float ts[64][65];
    const int t = threadIdx.x;
    const int bh = blockIdx.x >> 6, jt = blockIdx.x & 63;
#pragma unroll
    for (int s = 0; s < 4; ++s) {
        int idx = t + 256 * s;
        int jj = idx >> 4, q = idx & 15;
        float4 v = *(const float4*)(g_value +
            ((size_t)(bh >> 2) * NN + jt * 64 + jj) * HID + (bh & 3) * 64 + q * 4);
        ts[jj][q * 4 + 0] = v.x; ts[jj][q * 4 + 1] = v.y;
        ts[jj][q * 4 + 2] = v.z; ts[jj][q * 4 + 3] = v.w;
    }
    __syncthreads();
    const int k = t >> 2, seg = t & 3;
    uint32_t uh[8], ul[8];
#pragma unroll
    for (int e = 0; e < 8; ++e) {
        float v0 = ts[seg * 16 + 2 * e][k], v1 = ts[seg * 16 + 2 * e + 1][k];
        __half h0 = __float2half_rn(v0), h1 = __float2half_rn(v1);
        uh[e] = pk(h0, h1);
        ul[e] = pk(__float2half_rn(v0 - __half2float(h0)),
                   __float2half_rn(v1 - __half2float(h1)));
    }
    size_t dst = ((size_t)(bh * 64 + k)) * NN + jt * 64 + seg * 16;
    *(uint4*)(g_vhi + dst)     = make_uint4(uh[0], uh[1], uh[2], uh[3]);
    *(uint4*)(g_vhi + dst + 8) = make_uint4(uh[4], uh[5], uh[6], uh[7]);
    *(uint4*)(g_vlo + dst)     = make_uint4(ul[0], ul[1], ul[2], ul[3]);
    *(uint4*)(g_vlo + dst + 8) = make_uint4(ul[4], ul[5], ul[6], ul[7]);
}

// ---------------------------------------------------------------------------
// k_mma: CTA = (128 i, h, b). j-tiles of 32; 2-term HMMA: w_hi x (v_hi + v_lo)
// ---------------------------------------------------------------------------
__global__ void __launch_bounds__(256, 2) k_mma(const float* __restrict__ m,
                                                const float* __restrict__ r,
                                                float* __restrict__ out) {
    extern __shared__ __align__(16) char sgen[];
    __shared__ float thr_s[128];
    const int t = threadIdx.x, warp = t >> 5, lane = t & 31;
    const int h = blockIdx.y, bz = blockIdx.z;
    const int i_base = blockIdx.x * 128;
    const int bh64 = (bz * 4 + h) * 64;
    const uint32_t sb = (uint32_t)__cvta_generic_to_shared(sgen);

    const float rv = r[h], r2 = __fmul_rn(rv, rv);
    if (t < 128) {
        float2 st = g_stats[bz * NN + i_base + t];
        thr_s[t] = __fadd_rn(__fmul_rn(0.5f, __fmul_rn(r2, st.x)),
                             __fmul_rn(0.5f, __fmul_rn(r2, st.y)));
    }
    __syncthreads();

    const int i = t & 127, jh = t >> 7;
    const float* mbase = m + (size_t)(bz * NN + i_base) * NN;
    const float thr_i = thr_s[i];
    float den_acc = 0.f;
    float acc[32];
#pragma unroll
    for (int q = 0; q < 32; ++q) acc[q] = 0.f;

    {
#pragma unroll
        for (int s = 0; s < 4; ++s) {
            int idx = t + 256 * s;
            int i2 = idx >> 3, q = idx & 7;
            cpa16(sb + MOF + (unsigned)i2 * 144u + (unsigned)q * 16u,
                  mbase + (size_t)i2 * NN + q * 4);
        }
        int k2 = t >> 2, q = t & 3;
        cpa16(sb + VHO + (unsigned)k2 * 80u + (unsigned)q * 16u,
              g_vhi + (size_t)(bh64 + k2) * NN + q * 8);
        cpa16(sb + VLO + (unsigned)k2 * 80u + (unsigned)q * 16u,
              g_vlo + (size_t)(bh64 + k2) * NN + q * 8);
        asm volatile("cp.async.commit_group;");
    }

    for (int c = 0; c < 128; ++c) {
        const unsigned buf = (unsigned)(c & 1);
        if (c < 127) {
            const int j0n = (c + 1) * 32;
            const unsigned nb = (unsigned)((c + 1) & 1);
#pragma unroll
            for (int s = 0; s < 4; ++s) {
                int idx = t + 256 * s;
                int i2 = idx >> 3, q = idx & 7;
                cpa16(sb + MOF + nb * MBS + (unsigned)i2 * 144u + (unsigned)q * 16u,
                      mbase + (size_t)i2 * NN + j0n + q * 4);
            }
            int k2 = t >> 2, q = t & 3;
            cpa16(sb + VHO + nb * VBS + (unsigned)k2 * 80u + (unsigned)q * 16u,
                  g_vhi + (size_t)(bh64 + k2) * NN + j0n + q * 8);
            cpa16(sb + VLO + nb * VBS + (unsigned)k2 * 80u + (unsigned)q * 16u,
                  g_vlo + (size_t)(bh64 + k2) * NN + j0n + q * 8);
            asm volatile("cp.async.commit_group;");
            asm volatile("cp.async.wait_group 1;");
        } else {
            asm volatile("cp.async.wait_group 0;");
        }
        __syncthreads();

        // w-stage: exp/mask, fp16-hi only, den accumulate
        {
            const float* ms = (const float*)(sgen + MOF + buf * MBS) + i * 36 + jh * 16;
            float w[16];
#pragma unroll
            for (int q = 0; q < 4; ++q) {
                float4 mv = *(const float4*)(ms + q * 4);
                float s0 = __fmul_rn(mv.x, r2), s1 = __fmul_rn(mv.y, r2);
                float s2 = __fmul_rn(mv.z, r2), s3 = __fmul_rn(mv.w, r2);
                w[q * 4 + 0] = (s0 <= thr_i) ? __expf(-s0) : 0.f;
                w[q * 4 + 1] = (s1 <= thr_i) ? __expf(-s1) : 0.f;
                w[q * 4 + 2] = (s2 <= thr_i) ? __expf(-s2) : 0.f;
                w[q * 4 + 3] = (s3 <= thr_i) ? __expf(-s3) : 0.f;
            }
#pragma unroll
            for (int q = 0; q < 16; ++q) den_acc += w[q];
            uint32_t uh[8];
#pragma unroll
            for (int e = 0; e < 8; ++e)
                uh[e] = pk(__float2half_rn(w[2 * e]), __float2half_rn(w[2 * e + 1]));
            char* wd = sgen + WHO + buf * WBS + i * 80 + jh * 32;
            *(uint4*)wd        = make_uint4(uh[0], uh[1], uh[2], uh[3]);
            *(uint4*)(wd + 16) = make_uint4(uh[4], uh[5], uh[6], uh[7]);
        }
        __syncthreads();

        // mma stage: 2 terms (w_hi x v_hi, w_hi x v_lo)
        {
            const int i0 = warp * 16;
            const unsigned arow = (unsigned)(i0 + (lane & 15)) * 80u +
                                  (unsigned)((lane >> 4) << 4);
            const int nb_ = (lane & 7) + ((lane >> 4) << 3);
            const unsigned brow0 = (unsigned)nb_ * 80u + (unsigned)((lane & 8) << 1);
#pragma unroll
            for (int cc = 0; cc < 2; ++cc) {
                uint32_t ah0, ah1, ah2, ah3;
                uint32_t aaddr = sb + WHO + buf * WBS + arow + (unsigned)cc * 32u;
                LDSM4(ah0, ah1, ah2, ah3, aaddr);
#pragma unroll
                for (int g = 0; g < 4; ++g) {
                    uint32_t bh0, bh1, bh2, bh3, bl0, bl1, bl2, bl3;
                    uint32_t baddr = sb + VHO + buf * VBS + brow0 +
                                     (unsigned)(g * 16) * 80u + (unsigned)cc * 32u;
                    LDSM4(bh0, bh1, bh2, bh3, baddr);
                    LDSM4(bl0, bl1, bl2, bl3, baddr + (VLO - VHO));
                    float* d0 = acc + g * 8;
                    float* d1 = acc + g * 8 + 4;
                    MMA(d0, ah0, ah1, ah2, ah3, bh0, bh1);
                    MMA(d0, ah0, ah1, ah2, ah3, bl0, bl1);
                    MMA(d1, ah0, ah1, ah2, ah3, bh2, bh3);
                    MMA(d1, ah0, ah1, ah2, ah3, bl2, bl3);
                }
            }
        }
        __syncthreads();
    }

    float* sden = (float*)sgen;
    sden[t] = den_acc;
    __syncthreads();
    if (t < 128) sden[256 + t] = sden[t] + sden[t + 128];
    __syncthreads();
    const float* dden = sden + 256;
    const int i0 = warp * 16;
    const int r0 = lane >> 2, c0 = (lane & 3) * 2;
    const float inv0 = 1.0f / dden[i0 + r0];
    const float inv1 = 1.0f / dden[i0 + r0 + 8];
    float* ob = out + ((size_t)(bz * NN + i_base + i0)) * HID + h * 64;
#pragma unroll
    for (int nt = 0; nt < 8; ++nt) {
        float v0 = acc[nt * 4 + 0] * inv0, v1 = acc[nt * 4 + 1] * inv0;
        float v2 = acc[nt * 4 + 2] * inv1, v3 = acc[nt * 4 + 3] * inv1;
        float g0 = 0.5f * v0 * (1.0f + erff(v0 * 0.7071067811865475f));
        float g1 = 0.5f * v1 * (1.0f + erff(v1 * 0.7071067811865475f));
        float g2 = 0.5f * v2 * (1.0f + erff(v2 * 0.7071067811865475f));
        float g3 = 0.5f * v3 * (1.0f + erff(v3 * 0.7071067811865475f));
        *(float2*)(ob + (size_t)r0 * HID + nt * 8 + c0)       = make_float2(g0, g1);
        *(float2*)(ob + (size_t)(r0 + 8) * HID + nt * 8 + c0) = make_float2(g2, g3);
    }
}

// ---------------------------------------------------------------------------
extern "C" void kernel_launch(void* const* d_in, const int* in_sizes, int n_in,
                              void* d_out, int out_size) {
    const float *m = nullptr, *x = nullptr, *r = nullptr, *w = nullptr;
    for (int i = 0; i < n_in; ++i) {
        int s = in_sizes[i];
        if      (s == 33554432) m = (const float*)d_in[i];
        else if (s == 2097152)  x = (const float*)d_in[i];
        else if (s == 4)        r = (const float*)d_in[i];
        else if (s == 65536)    w = (const float*)d_in[i];
    }
    float* out = (float*)d_out;

    cudaFuncSetAttribute(k_mma, cudaFuncAttributeMaxDynamicSharedMemorySize, SMT);

    k_pre<<<256 + 8192, 256>>>(x, w, m);
    k_vt<<<512, 256>>>();
    k_mma<<<dim3(32, 4, 2), 256, SMT>>>(m, r, out);
}